// round 12
// baseline (speedup 1.0000x reference)
#include <cuda_runtime.h>
#include <cuda_fp16.h>
#include <stdint.h>

#define T_     2048
#define EMB_   1024
#define HEADS_ 16
#define HD_    64
#define B_     2
#define M_     (B_*T_)      // 4096
#define BH_    (B_*HEADS_)  // 32
#define QSCALE 0.18033688f  // log2(e) / 8

// ---------------- scratch --------------------------------------------------
__device__ __half g_Qh[BH_*T_*HD_];   // [bh][t][d], pre-scaled by QSCALE
__device__ __half g_Kh[BH_*T_*HD_];   // [bh][t][d]
__device__ __half g_Vh[BH_*HD_*T_];   // [bh][d][t]
__device__ __half g_Ah[(size_t)M_*EMB_];   // attention out, fp16 [m][emb]
__device__ __half g_x16[(size_t)M_*EMB_];
__device__ __half g_w16[(size_t)3*EMB_*EMB_];
__device__ __half g_wo16[(size_t)EMB_*EMB_];

// ---------------- helpers ---------------------------------------------------
__device__ __forceinline__ uint32_t smem_u32(const void* p) {
    uint32_t a;
    asm("{ .reg .u64 t; cvta.to.shared.u64 t, %1; cvt.u32.u64 %0, t; }" : "=r"(a) : "l"(p));
    return a;
}
__device__ __forceinline__ void cp16(uint32_t dst, const void* src) {
    asm volatile("cp.async.cg.shared.global [%0], [%1], 16;" :: "r"(dst), "l"(src));
}
__device__ __forceinline__ void cp_commit() { asm volatile("cp.async.commit_group;" ::: "memory"); }
template<int N> __device__ __forceinline__ void cp_wait() {
    asm volatile("cp.async.wait_group %0;" :: "n"(N) : "memory");
}
__device__ __forceinline__ void mma_f16(float* c, const uint32_t* a, const uint32_t* b) {
    asm volatile("mma.sync.aligned.m16n8k16.row.col.f32.f16.f16.f32 "
        "{%0,%1,%2,%3}, {%4,%5,%6,%7}, {%8,%9}, {%0,%1,%2,%3};"
        : "+f"(c[0]), "+f"(c[1]), "+f"(c[2]), "+f"(c[3])
        : "r"(a[0]), "r"(a[1]), "r"(a[2]), "r"(a[3]), "r"(b[0]), "r"(b[1]));
}
__device__ __forceinline__ void ldsm_x4(uint32_t* r, uint32_t addr) {
    asm volatile("ldmatrix.sync.aligned.m8n8.x4.shared.b16 {%0,%1,%2,%3}, [%4];"
        : "=r"(r[0]), "=r"(r[1]), "=r"(r[2]), "=r"(r[3]) : "r"(addr));
}
__device__ __forceinline__ float ex2f(float x) {
    float y; asm("ex2.approx.ftz.f32 %0, %1;" : "=f"(y) : "f"(x)); return y;
}
__device__ __forceinline__ uint32_t packh2(float a, float b) {
    __half2 h = __floats2half2_rn(a, b);
    return *(uint32_t*)&h;
}

// ---------------- fused fp32 -> fp16 convert (one launch) -------------------
__global__ void tohalf_all(const float* __restrict__ x,
                           const float* __restrict__ Wq, const float* __restrict__ Wk,
                           const float* __restrict__ Wv, const float* __restrict__ Wo,
                           __half* __restrict__ x16, __half* __restrict__ w16,
                           __half* __restrict__ wo16)
{
    const int NE = M_ * EMB_;          // 4M
    const int NW = EMB_ * EMB_;        // 1M
    int i = (blockIdx.x * blockDim.x + threadIdx.x) << 2;
    const float* s;
    __half* d;
    if (i < NE) { s = x + i; d = x16 + i; }
    else {
        int j = i - NE;
        if (j < 3 * NW) {
            const int sel = j >> 20;             // NW == 2^20
            const int off = j & (NW - 1);
            s = (sel == 0 ? Wq : (sel == 1 ? Wk : Wv)) + off;
            d = w16 + j;
        } else {
            int off = j - 3 * NW;
            if (off >= NW) return;
            s = Wo + off; d = wo16 + off;
        }
    }
    float4 v = *(const float4*)s;
    __half2* D = (__half2*)d;
    D[0] = __floats2half2_rn(v.x, v.y);
    D[1] = __floats2half2_rn(v.z, v.w);
}

// ---------------- fp16 HMMA GEMM: 128x64 tile, K=1024, 2-stage, ldmatrix ----
// register-fragment double buffering inside each chunk
#define BK      64
#define NCH     (EMB_/BK)       // 16
#define GST     72              // half stride (64 + 8 pad); 144B rows
#define A_E     (128*GST)
#define B_E     (64*GST)
#define GBUF_E  (A_E + B_E)
#define GEMM_SMEM (2*GBUF_E*2)  // 55296 bytes

template<int MODE>
__global__ void __launch_bounds__(256, 3) gemm_h(
    const __half* __restrict__ A, const __half* __restrict__ W,
    const float* __restrict__ b0, const float* __restrict__ b1,
    const float* __restrict__ b2,
    __half* __restrict__ qo, __half* __restrict__ ko, __half* __restrict__ vo,
    float* __restrict__ fout)
{
    extern __shared__ __half sh[];
    const int tid  = threadIdx.x;
    const int lane = tid & 31;
    const int wid  = tid >> 5;
    const int wm   = wid >> 1;       // 0..3
    const int wn   = wid & 1;        // 0..1
    const int m0   = blockIdx.y << 7;
    const int n0   = blockIdx.x << 6;
    const int z    = (MODE == 0) ? (int)blockIdx.z : 0;

    const __half* Wp  = W + (size_t)z * EMB_ * EMB_;
    const float* bias = (MODE == 0) ? (z == 0 ? b0 : (z == 1 ? b1 : b2)) : b0;

    const uint32_t sb = smem_u32(sh);

    const uint32_t rowA = (uint32_t)(((lane >> 3) & 1) * 8 + (lane & 7));
    const uint32_t kA   = (uint32_t)((lane >> 4) * 16);
    const uint32_t rowB = (uint32_t)((lane >> 4) * 8 + (lane & 7));
    const uint32_t kB   = (uint32_t)(((lane >> 3) & 1) * 16);

    auto load_chunk = [&](int kc, int buf) {
        const uint32_t base = sb + (uint32_t)buf * (GBUF_E * 2);
        const int ke = kc * BK;
#pragma unroll
        for (int it = 0; it < 6; it++) {
            const int idx = tid + (it << 8);
            const int row = idx >> 3;
            const int seg = idx & 7;
            const __half* src = (row < 128)
                ? (A  + (size_t)(m0 + row) * EMB_ + ke + seg * 8)
                : (Wp + (size_t)(n0 + row - 128) * EMB_ + ke + seg * 8);
            cp16(base + (uint32_t)row * 144 + seg * 16, src);
        }
        cp_commit();
    };

    float acc[2][4][4] = {};
    load_chunk(0, 0);

    for (int kc = 0; kc < NCH; kc++) {
        const int buf = kc & 1;
        if (kc + 1 < NCH) { load_chunk(kc + 1, buf ^ 1); cp_wait<1>(); }
        else              { cp_wait<0>(); }
        __syncthreads();

        const uint32_t sAu = sb + (uint32_t)buf * (GBUF_E * 2);
        const uint32_t sBu = sAu + A_E * 2;

        uint32_t aF[2][2][4], bF[2][4][2];
        // preload ks = 0 fragments
#pragma unroll
        for (int np = 0; np < 2; np++) {
            uint32_t r4[4];
            ldsm_x4(r4, sBu + (uint32_t)(wn*32 + np*16 + rowB) * 144 + kB);
            bF[0][np*2  ][0] = r4[0]; bF[0][np*2  ][1] = r4[1];
            bF[0][np*2+1][0] = r4[2]; bF[0][np*2+1][1] = r4[3];
        }
#pragma unroll
        for (int mf = 0; mf < 2; mf++)
            ldsm_x4(aF[0][mf], sAu + (uint32_t)(wm*32 + mf*16 + rowA) * 144 + kA);

#pragma unroll
        for (int ks = 0; ks < 4; ks++) {
            const int cur = ks & 1, nx = cur ^ 1;
            if (ks < 3) {
                const uint32_t kb2 = (uint32_t)(ks + 1) * 32;
#pragma unroll
                for (int np = 0; np < 2; np++) {
                    uint32_t r4[4];
                    ldsm_x4(r4, sBu + (uint32_t)(wn*32 + np*16 + rowB) * 144 + kB + kb2);
                    bF[nx][np*2  ][0] = r4[0]; bF[nx][np*2  ][1] = r4[1];
                    bF[nx][np*2+1][0] = r4[2]; bF[nx][np*2+1][1] = r4[3];
                }
#pragma unroll
                for (int mf = 0; mf < 2; mf++)
                    ldsm_x4(aF[nx][mf], sAu + (uint32_t)(wm*32 + mf*16 + rowA) * 144 + kA + kb2);
            }
#pragma unroll
            for (int mf = 0; mf < 2; mf++)
#pragma unroll
                for (int nf = 0; nf < 4; nf++)
                    mma_f16(acc[mf][nf], aF[cur][mf], bF[cur][nf]);
        }
        __syncthreads();
    }

    // -------- epilogue --------
#pragma unroll
    for (int mf = 0; mf < 2; mf++) {
#pragma unroll
        for (int nf = 0; nf < 4; nf++) {
#pragma unroll
            for (int h = 0; h < 2; h++) {
                const int m = m0 + wm * 32 + mf * 16 + (lane >> 2) + h * 8;
                const int n = n0 + wn * 32 + nf * 8 + ((lane & 3) << 1);
                const float v0 = acc[mf][nf][h*2 + 0] + bias[n];
                const float v1 = acc[mf][nf][h*2 + 1] + bias[n + 1];
                if (MODE == 0) {
                    const int bb = m >> 11, t = m & (T_ - 1);
                    const int hh = n >> 6,  d = n & 63;
                    const int bh = bb * HEADS_ + hh;
                    if (z == 0) {
                        *(uint32_t*)&qo[((size_t)bh * T_ + t) * HD_ + d] =
                            packh2(v0 * QSCALE, v1 * QSCALE);
                    } else if (z == 1) {
                        *(uint32_t*)&ko[((size_t)bh * T_ + t) * HD_ + d] =
                            packh2(v0, v1);
                    } else {
                        vo[((size_t)bh * HD_ + d    ) * T_ + t] = __float2half(v0);
                        vo[((size_t)bh * HD_ + d + 1) * T_ + t] = __float2half(v1);
                    }
                } else {
                    *(float2*)&fout[(size_t)m * EMB_ + n] = make_float2(v0, v1);
                }
            }
        }
    }
}

// ---------------- HMMA flash attention, 3-stage KV, single-sync, 1D grid ----
// register-fragment double buffering in S and PV phases
#define FST 72
#define FQ_E (128*FST)                      // 9216 halves
#define FKV_E (64*FST)                      // 4608 halves per K (or V) tile
#define FBUF_E (2*FKV_E)                    // K + V per stage
#define FLASH_SMEM ((FQ_E + 3*FBUF_E)*2)    // 73728 bytes -> 3 CTAs/SM

__global__ void __launch_bounds__(128, 3) flash_h(
    const __half* __restrict__ Q, const __half* __restrict__ K,
    const __half* __restrict__ V, __half* __restrict__ Aout)
{
    extern __shared__ __half fsh[];
    __half* Qs  = fsh;                  // [128][72]
    __half* KVs = fsh + FQ_E;           // 3 stages of (K[64][72], V[64][72])

    const int idx = blockIdx.x;
    const int qi  = (T_/128 - 1) - (idx >> 5);
    const int bh  = idx & 31;
    const int q0  = qi << 7;
    const int tid = threadIdx.x;
    const int lane = tid & 31;
    const int w   = tid >> 5;
    const int njt = 2 * qi + 2;

    const __half* Qg = Q + ((size_t)bh * T_ + q0) * HD_;
    const __half* Kg = K + (size_t)bh * T_ * HD_;
    const __half* Vg = V + (size_t)bh * HD_ * T_;
    const uint32_t sQ  = smem_u32(Qs);
    const uint32_t sKV = smem_u32(KVs);

    const uint32_t rowA = (uint32_t)(((lane >> 3) & 1) * 8 + (lane & 7));
    const uint32_t kA   = (uint32_t)((lane >> 4) * 16);
    const uint32_t rowB = (uint32_t)((lane >> 4) * 8 + (lane & 7));
    const uint32_t kB   = (uint32_t)(((lane >> 3) & 1) * 16);

#pragma unroll
    for (int s = 0; s < 8; s++)
        cp16(sQ + (uint32_t)tid*144 + s*16, Qg + (size_t)tid*HD_ + s*8);
    cp_commit();

    auto loadKV = [&](int jt, int buf) {
        const int k0 = jt << 6;
        const int r  = tid >> 1;
        const int sb_ = (tid & 1) << 2;
        const uint32_t base = sKV + (uint32_t)buf * (FBUF_E * 2);
#pragma unroll
        for (int s = sb_; s < sb_ + 4; s++) {
            cp16(base + (uint32_t)r*144 + s*16, Kg + (size_t)(k0 + r)*HD_ + s*8);
            cp16(base + FKV_E*2 + (uint32_t)r*144 + s*16, Vg + (size_t)r*T_ + k0 + s*8);
        }
        cp_commit();
    };
    loadKV(0, 0);

    float o[2][8][4] = {};
    float mi[2][2], li[2][2];
#pragma unroll
    for (int a = 0; a < 2; a++)
#pragma unroll
        for (int b = 0; b < 2; b++) { mi[a][b] = -1e30f; li[a][b] = 0.f; }

    for (int jt = 0; jt < njt; jt++) {
        if (jt + 1 < njt) { loadKV(jt + 1, (jt + 1) % 3); cp_wait<1>(); }
        else              { cp_wait<0>(); }
        __syncthreads();

        const uint32_t Kb = sKV + (uint32_t)(jt % 3) * (FBUF_E * 2);
        const uint32_t Vb = Kb + FKV_E * 2;

        // ---- S = Q @ K^T (log2-scaled), frag double-buffered ----
        float s[2][8][4] = {};
        {
            uint32_t aF[2][2][4], bF[2][8][2];
#pragma unroll
            for (int np = 0; np < 4; np++) {
                uint32_t r4[4];
                ldsm_x4(r4, Kb + (uint32_t)(np*16 + rowB) * 144 + kB);
                bF[0][np*2  ][0] = r4[0]; bF[0][np*2  ][1] = r4[1];
                bF[0][np*2+1][0] = r4[2]; bF[0][np*2+1][1] = r4[3];
            }
#pragma unroll
            for (int mf = 0; mf < 2; mf++)
                ldsm_x4(aF[0][mf], sQ + (uint32_t)(w*32 + mf*16 + rowA) * 144 + kA);

#pragma unroll
            for (int ks = 0; ks < 4; ks++) {
                const int cur = ks & 1, nx = cur ^ 1;
                if (ks < 3) {
                    const uint32_t kb2 = (uint32_t)(ks + 1) * 32;
#pragma unroll
                    for (int np = 0; np < 4; np++) {
                        uint32_t r4[4];
                        ldsm_x4(r4, Kb + (uint32_t)(np*16 + rowB) * 144 + kB + kb2);
                        bF[nx][np*2  ][0] = r4[0]; bF[nx][np*2  ][1] = r4[1];
                        bF[nx][np*2+1][0] = r4[2]; bF[nx][np*2+1][1] = r4[3];
                    }
#pragma unroll
                    for (int mf = 0; mf < 2; mf++)
                        ldsm_x4(aF[nx][mf], sQ + (uint32_t)(w*32 + mf*16 + rowA) * 144 + kA + kb2);
                }
#pragma unroll
                for (int mf = 0; mf < 2; mf++)
#pragma unroll
                    for (int nf = 0; nf < 8; nf++)
                        mma_f16(s[mf][nf], aF[cur][mf], bF[cur][nf]);
            }
        }

        // ---- causal mask (only last 2 tiles touch the diagonal) ----
        const int k0 = jt << 6;
        if (jt >= njt - 2) {
#pragma unroll
            for (int mf = 0; mf < 2; mf++)
#pragma unroll
                for (int nf = 0; nf < 8; nf++)
#pragma unroll
                    for (int c = 0; c < 4; c++) {
                        const int qr = q0 + w * 32 + mf * 16 + (lane >> 2) + (c >> 1) * 8;
                        const int kc = k0 + nf * 8 + ((lane & 3) << 1) + (c & 1);
                        if (kc > qr) s[mf][nf][c] = -1e30f;
                    }
        }

        // ---- online softmax ----
        float fac[2][2];
#pragma unroll
        for (int mf = 0; mf < 2; mf++)
#pragma unroll
            for (int h = 0; h < 2; h++) {
                float mx = -1e30f;
#pragma unroll
                for (int nf = 0; nf < 8; nf++)
                    mx = fmaxf(mx, fmaxf(s[mf][nf][2*h], s[mf][nf][2*h + 1]));
                mx = fmaxf(mx, __shfl_xor_sync(0xffffffffu, mx, 1));
                mx = fmaxf(mx, __shfl_xor_sync(0xffffffffu, mx, 2));
                const float mn = fmaxf(mi[mf][h], mx);
                fac[mf][h] = ex2f(mi[mf][h] - mn);
                mi[mf][h] = mn;
            }
#pragma unroll
        for (int mf = 0; mf < 2; mf++)
#pragma unroll
            for (int h = 0; h < 2; h++) {
                float r = 0.f;
#pragma unroll
                for (int nf = 0; nf < 8; nf++) {
                    float p0 = ex2f(s[mf][nf][2*h]     - mi[mf][h]);
                    float p1 = ex2f(s[mf][nf][2*h + 1] - mi[mf][h]);
                    s[mf][nf][2*h]     = p0;
                    s[mf][nf][2*h + 1] = p1;
                    r += p0 + p1;
                }
                r += __shfl_xor_sync(0xffffffffu, r, 1);
                r += __shfl_xor_sync(0xffffffffu, r, 2);
                li[mf][h] = li[mf][h] * fac[mf][h] + r;
            }
#pragma unroll
        for (int mf = 0; mf < 2; mf++)
#pragma unroll
            for (int df = 0; df < 8; df++) {
                o[mf][df][0] *= fac[mf][0]; o[mf][df][1] *= fac[mf][0];
                o[mf][df][2] *= fac[mf][1]; o[mf][df][3] *= fac[mf][1];
            }

        // ---- O += P @ V  (frag double-buffered V) ----
        {
            uint32_t vF[2][8][2];
#pragma unroll
            for (int np = 0; np < 4; np++) {
                uint32_t r4[4];
                ldsm_x4(r4, Vb + (uint32_t)(np*16 + rowB) * 144 + kB);
                vF[0][np*2  ][0] = r4[0]; vF[0][np*2  ][1] = r4[1];
                vF[0][np*2+1][0] = r4[2]; vF[0][np*2+1][1] = r4[3];
            }
#pragma unroll
            for (int kf = 0; kf < 4; kf++) {
                const int cur = kf & 1, nx = cur ^ 1;
                if (kf < 3) {
                    const uint32_t kb2 = (uint32_t)(kf + 1) * 32;
#pragma unroll
                    for (int np = 0; np < 4; np++) {
                        uint32_t r4[4];
                        ldsm_x4(r4, Vb + (uint32_t)(np*16 + rowB) * 144 + kB + kb2);
                        vF[nx][np*2  ][0] = r4[0]; vF[nx][np*2  ][1] = r4[1];
                        vF[nx][np*2+1][0] = r4[2]; vF[nx][np*2+1][1] = r4[3];
                    }
                }
#pragma unroll
                for (int mf = 0; mf < 2; mf++) {
                    uint32_t pa[4];
                    pa[0] = packh2(s[mf][2*kf][0],     s[mf][2*kf][1]);
                    pa[1] = packh2(s[mf][2*kf][2],     s[mf][2*kf][3]);
                    pa[2] = packh2(s[mf][2*kf + 1][0], s[mf][2*kf + 1][1]);
                    pa[3] = packh2(s[mf][2*kf + 1][2], s[mf][2*kf + 1][3]);
#pragma unroll
                    for (int df = 0; df < 8; df++)
                        mma_f16(o[mf][df], pa, vF[cur][df]);
                }
            }
        }
    }

    // ---- write O/li -> fp16 A [m][emb] ----
    const int bidx = bh >> 4;
    const int hh   = bh & 15;
    float inv[2][2];
#pragma unroll
    for (int mf = 0; mf < 2; mf++)
#pragma unroll
        for (int h = 0; h < 2; h++) inv[mf][h] = __frcp_rn(li[mf][h]);

#pragma unroll
    for (int mf = 0; mf < 2; mf++)
#pragma unroll
        for (int h = 0; h < 2; h++) {
            const int t = q0 + w * 32 + mf * 16 + (lane >> 2) + h * 8;
            const size_t m = (size_t)bidx * T_ + t;
#pragma unroll
            for (int df = 0; df < 8; df++) {
                const int col = hh * 64 + df * 8 + ((lane & 3) << 1);
                *(uint32_t*)&Aout[m * EMB_ + col] =
                    packh2(o[mf][df][2*h] * inv[mf][h], o[mf][df][2*h + 1] * inv[mf][h]);
            }
        }
}

// ---------------------------------------------------------------------------
extern "C" void kernel_launch(void* const* d_in, const int* in_sizes, int n_in,
                              void* d_out, int out_size)
{
    const float* x  = (const float*)d_in[0];
    const float* Wq = (const float*)d_in[1];
    const float* bq = (const float*)d_in[2];
    const float* Wk = (const float*)d_in[3];
    const float* bk = (const float*)d_in[4];
    const float* Wv = (const float*)d_in[5];
    const float* bv = (const float*)d_in[6];
    const float* Wo = (const float*)d_in[7];
    const float* bo = (const float*)d_in[8];
    float* out = (float*)d_out;

    __half *qh, *kh, *vh, *ah, *x16, *w16, *wo16;
    cudaGetSymbolAddress((void**)&qh,   g_Qh);
    cudaGetSymbolAddress((void**)&kh,   g_Kh);
    cudaGetSymbolAddress((void**)&vh,   g_Vh);
    cudaGetSymbolAddress((void**)&ah,   g_Ah);
    cudaGetSymbolAddress((void**)&x16,  g_x16);
    cudaGetSymbolAddress((void**)&w16,  g_w16);
    cudaGetSymbolAddress((void**)&wo16, g_wo16);

    cudaFuncSetAttribute(flash_h,   cudaFuncAttributeMaxDynamicSharedMemorySize, FLASH_SMEM);
    cudaFuncSetAttribute(gemm_h<0>, cudaFuncAttributeMaxDynamicSharedMemorySize, GEMM_SMEM);
    cudaFuncSetAttribute(gemm_h<1>, cudaFuncAttributeMaxDynamicSharedMemorySize, GEMM_SMEM);

    const int NE = M_ * EMB_;
    const int NW = EMB_ * EMB_;
    const int TOT4 = (NE + 4*NW) / 4;

    tohalf_all<<<(TOT4 + 255)/256, 256>>>(x, Wq, Wk, Wv, Wo, x16, w16, wo16);

    gemm_h<0><<<dim3(EMB_/64, M_/128, 3), 256, GEMM_SMEM>>>(
        x16, w16, bq, bk, bv, qh, kh, vh, nullptr);

    flash_h<<<dim3((T_/128) * BH_), 128, FLASH_SMEM>>>(qh, kh, vh, ah);

    gemm_h<1><<<dim3(EMB_/64, M_/128, 1), 256, GEMM_SMEM>>>(
        ah, wo16, bo, bo, bo, nullptr, nullptr, nullptr, out);
}

// round 13
// speedup vs baseline: 1.0320x; 1.0320x over previous
#include <cuda_runtime.h>
#include <cuda_fp16.h>
#include <stdint.h>

#define T_     2048
#define EMB_   1024
#define HEADS_ 16
#define HD_    64
#define B_     2
#define M_     (B_*T_)      // 4096
#define BH_    (B_*HEADS_)  // 32
#define QSCALE 0.18033688f  // log2(e) / 8

// ---------------- scratch --------------------------------------------------
__device__ __half g_Qh[BH_*T_*HD_];   // [bh][t][d], pre-scaled by QSCALE
__device__ __half g_Kh[BH_*T_*HD_];   // [bh][t][d]
__device__ __half g_Vh[BH_*T_*HD_];   // [bh][t][d]  (same layout as K)
__device__ __half g_Ah[(size_t)M_*EMB_];   // attention out, fp16 [m][emb]
__device__ __half g_x16[(size_t)M_*EMB_];
__device__ __half g_w16[(size_t)3*EMB_*EMB_];
__device__ __half g_wo16[(size_t)EMB_*EMB_];

// ---------------- helpers ---------------------------------------------------
__device__ __forceinline__ uint32_t smem_u32(const void* p) {
    uint32_t a;
    asm("{ .reg .u64 t; cvta.to.shared.u64 t, %1; cvt.u32.u64 %0, t; }" : "=r"(a) : "l"(p));
    return a;
}
__device__ __forceinline__ void cp16(uint32_t dst, const void* src) {
    asm volatile("cp.async.cg.shared.global [%0], [%1], 16;" :: "r"(dst), "l"(src));
}
__device__ __forceinline__ void cp_commit() { asm volatile("cp.async.commit_group;" ::: "memory"); }
template<int N> __device__ __forceinline__ void cp_wait() {
    asm volatile("cp.async.wait_group %0;" :: "n"(N) : "memory");
}
__device__ __forceinline__ void mma_f16(float* c, const uint32_t* a, const uint32_t* b) {
    asm volatile("mma.sync.aligned.m16n8k16.row.col.f32.f16.f16.f32 "
        "{%0,%1,%2,%3}, {%4,%5,%6,%7}, {%8,%9}, {%0,%1,%2,%3};"
        : "+f"(c[0]), "+f"(c[1]), "+f"(c[2]), "+f"(c[3])
        : "r"(a[0]), "r"(a[1]), "r"(a[2]), "r"(a[3]), "r"(b[0]), "r"(b[1]));
}
__device__ __forceinline__ void ldsm_x4(uint32_t* r, uint32_t addr) {
    asm volatile("ldmatrix.sync.aligned.m8n8.x4.shared.b16 {%0,%1,%2,%3}, [%4];"
        : "=r"(r[0]), "=r"(r[1]), "=r"(r[2]), "=r"(r[3]) : "r"(addr));
}
__device__ __forceinline__ void ldsm_x4_t(uint32_t* r, uint32_t addr) {
    asm volatile("ldmatrix.sync.aligned.m8n8.x4.trans.shared.b16 {%0,%1,%2,%3}, [%4];"
        : "=r"(r[0]), "=r"(r[1]), "=r"(r[2]), "=r"(r[3]) : "r"(addr));
}
__device__ __forceinline__ float ex2f(float x) {
    float y; asm("ex2.approx.ftz.f32 %0, %1;" : "=f"(y) : "f"(x)); return y;
}
__device__ __forceinline__ uint32_t packh2(float a, float b) {
    __half2 h = __floats2half2_rn(a, b);
    return *(uint32_t*)&h;
}

// ---------------- fused fp32 -> fp16 convert (one launch) -------------------
__global__ void tohalf_all(const float* __restrict__ x,
                           const float* __restrict__ Wq, const float* __restrict__ Wk,
                           const float* __restrict__ Wv, const float* __restrict__ Wo,
                           __half* __restrict__ x16, __half* __restrict__ w16,
                           __half* __restrict__ wo16)
{
    const int NE = M_ * EMB_;          // 4M
    const int NW = EMB_ * EMB_;        // 1M
    int i = (blockIdx.x * blockDim.x + threadIdx.x) << 2;
    const float* s;
    __half* d;
    if (i < NE) { s = x + i; d = x16 + i; }
    else {
        int j = i - NE;
        if (j < 3 * NW) {
            const int sel = j >> 20;             // NW == 2^20
            const int off = j & (NW - 1);
            s = (sel == 0 ? Wq : (sel == 1 ? Wk : Wv)) + off;
            d = w16 + j;
        } else {
            int off = j - 3 * NW;
            if (off >= NW) return;
            s = Wo + off; d = wo16 + off;
        }
    }
    float4 v = *(const float4*)s;
    __half2* D = (__half2*)d;
    D[0] = __floats2half2_rn(v.x, v.y);
    D[1] = __floats2half2_rn(v.z, v.w);
}

// ---------------- fp16 HMMA GEMM: 128x64 tile, K=1024, 2-stage, ldmatrix ----
#define BK      64
#define NCH     (EMB_/BK)       // 16
#define GST     72              // half stride (64 + 8 pad); 144B rows
#define A_E     (128*GST)
#define B_E     (64*GST)
#define GBUF_E  (A_E + B_E)
#define GEMM_SMEM (2*GBUF_E*2)  // 55296 bytes -> 4 CTAs/SM

template<int MODE>
__global__ void __launch_bounds__(256, 4) gemm_h(
    const __half* __restrict__ A, const __half* __restrict__ W,
    const float* __restrict__ b0, const float* __restrict__ b1,
    const float* __restrict__ b2,
    __half* __restrict__ qo, __half* __restrict__ ko, __half* __restrict__ vo,
    float* __restrict__ fout)
{
    extern __shared__ __half sh[];
    const int tid  = threadIdx.x;
    const int lane = tid & 31;
    const int wid  = tid >> 5;
    const int wm   = wid >> 1;       // 0..3
    const int wn   = wid & 1;        // 0..1
    const int m0   = blockIdx.y << 7;
    const int n0   = blockIdx.x << 6;
    const int z    = (MODE == 0) ? (int)blockIdx.z : 0;

    const __half* Wp  = W + (size_t)z * EMB_ * EMB_;
    const float* bias = (MODE == 0) ? (z == 0 ? b0 : (z == 1 ? b1 : b2)) : b0;

    const uint32_t sb = smem_u32(sh);

    const uint32_t rowA = (uint32_t)(((lane >> 3) & 1) * 8 + (lane & 7));
    const uint32_t kA   = (uint32_t)((lane >> 4) * 16);
    const uint32_t rowB = (uint32_t)((lane >> 4) * 8 + (lane & 7));
    const uint32_t kB   = (uint32_t)(((lane >> 3) & 1) * 16);

    auto load_chunk = [&](int kc, int buf) {
        const uint32_t base = sb + (uint32_t)buf * (GBUF_E * 2);
        const int ke = kc * BK;
#pragma unroll
        for (int it = 0; it < 6; it++) {
            const int idx = tid + (it << 8);
            const int row = idx >> 3;
            const int seg = idx & 7;
            const __half* src = (row < 128)
                ? (A  + (size_t)(m0 + row) * EMB_ + ke + seg * 8)
                : (Wp + (size_t)(n0 + row - 128) * EMB_ + ke + seg * 8);
            cp16(base + (uint32_t)row * 144 + seg * 16, src);
        }
        cp_commit();
    };

    float acc[2][4][4] = {};
    load_chunk(0, 0);

    for (int kc = 0; kc < NCH; kc++) {
        const int buf = kc & 1;
        if (kc + 1 < NCH) { load_chunk(kc + 1, buf ^ 1); cp_wait<1>(); }
        else              { cp_wait<0>(); }
        __syncthreads();

        const uint32_t sAu = sb + (uint32_t)buf * (GBUF_E * 2);
        const uint32_t sBu = sAu + A_E * 2;

#pragma unroll
        for (int ks = 0; ks < 4; ks++) {
            const uint32_t kb2 = (uint32_t)ks * 32;
            uint32_t bf[4][2];
#pragma unroll
            for (int np = 0; np < 2; np++) {
                uint32_t r4[4];
                ldsm_x4(r4, sBu + (uint32_t)(wn*32 + np*16 + rowB) * 144 + kB + kb2);
                bf[np*2  ][0] = r4[0]; bf[np*2  ][1] = r4[1];
                bf[np*2+1][0] = r4[2]; bf[np*2+1][1] = r4[3];
            }
#pragma unroll
            for (int mf = 0; mf < 2; mf++) {
                uint32_t a[4];
                ldsm_x4(a, sAu + (uint32_t)(wm*32 + mf*16 + rowA) * 144 + kA + kb2);
#pragma unroll
                for (int nf = 0; nf < 4; nf++)
                    mma_f16(acc[mf][nf], a, bf[nf]);
            }
        }
        __syncthreads();
    }

    // -------- epilogue --------
#pragma unroll
    for (int mf = 0; mf < 2; mf++) {
#pragma unroll
        for (int nf = 0; nf < 4; nf++) {
#pragma unroll
            for (int h = 0; h < 2; h++) {
                const int m = m0 + wm * 32 + mf * 16 + (lane >> 2) + h * 8;
                const int n = n0 + wn * 32 + nf * 8 + ((lane & 3) << 1);
                const float v0 = acc[mf][nf][h*2 + 0] + bias[n];
                const float v1 = acc[mf][nf][h*2 + 1] + bias[n + 1];
                if (MODE == 0) {
                    const int bb = m >> 11, t = m & (T_ - 1);
                    const int hh = n >> 6,  d = n & 63;
                    const int bh = bb * HEADS_ + hh;
                    if (z == 0) {
                        *(uint32_t*)&qo[((size_t)bh * T_ + t) * HD_ + d] =
                            packh2(v0 * QSCALE, v1 * QSCALE);
                    } else if (z == 1) {
                        *(uint32_t*)&ko[((size_t)bh * T_ + t) * HD_ + d] =
                            packh2(v0, v1);
                    } else {
                        *(uint32_t*)&vo[((size_t)bh * T_ + t) * HD_ + d] =
                            packh2(v0, v1);
                    }
                } else {
                    *(float2*)&fout[(size_t)m * EMB_ + n] = make_float2(v0, v1);
                }
            }
        }
    }
}

// ---------------- HMMA flash attention, 3-stage KV, single-sync, 1D grid ----
// V stored [bh][t][d]; PV B-fragments via ldmatrix.trans
#define FST 72
#define FQ_E (128*FST)                      // 9216 halves
#define FKV_E (64*FST)                      // 4608 halves per K (or V) tile
#define FBUF_E (2*FKV_E)                    // K + V per stage
#define FLASH_SMEM ((FQ_E + 3*FBUF_E)*2)    // 73728 bytes -> 3 CTAs/SM

__global__ void __launch_bounds__(128, 3) flash_h(
    const __half* __restrict__ Q, const __half* __restrict__ K,
    const __half* __restrict__ V, __half* __restrict__ Aout)
{
    extern __shared__ __half fsh[];
    __half* Qs  = fsh;                  // [128][72]
    __half* KVs = fsh + FQ_E;           // 3 stages of (K[64][72], V[64][72])

    // global heavy-first: idx 0..31 -> qi=15 (all bh), then qi=14, ...
    const int idx = blockIdx.x;
    const int qi  = (T_/128 - 1) - (idx >> 5);
    const int bh  = idx & 31;
    const int q0  = qi << 7;
    const int tid = threadIdx.x;
    const int lane = tid & 31;
    const int w   = tid >> 5;
    const int njt = 2 * qi + 2;

    const __half* Qg = Q + ((size_t)bh * T_ + q0) * HD_;
    const __half* Kg = K + (size_t)bh * T_ * HD_;
    const __half* Vg = V + (size_t)bh * T_ * HD_;
    const uint32_t sQ  = smem_u32(Qs);
    const uint32_t sKV = smem_u32(KVs);

    const uint32_t rowA = (uint32_t)(((lane >> 3) & 1) * 8 + (lane & 7));  // also V trans row
    const uint32_t kA   = (uint32_t)((lane >> 4) * 16);                    // also V trans n-off
    const uint32_t rowB = (uint32_t)((lane >> 4) * 8 + (lane & 7));
    const uint32_t kB   = (uint32_t)(((lane >> 3) & 1) * 16);

#pragma unroll
    for (int s = 0; s < 8; s++)
        cp16(sQ + (uint32_t)tid*144 + s*16, Qg + (size_t)tid*HD_ + s*8);
    cp_commit();

    auto loadKV = [&](int jt, int buf) {
        const int k0 = jt << 6;
        const int r  = tid >> 1;
        const int sb_ = (tid & 1) << 2;
        const uint32_t base = sKV + (uint32_t)buf * (FBUF_E * 2);
#pragma unroll
        for (int s = sb_; s < sb_ + 4; s++) {
            cp16(base + (uint32_t)r*144 + s*16, Kg + (size_t)(k0 + r)*HD_ + s*8);
            cp16(base + FKV_E*2 + (uint32_t)r*144 + s*16, Vg + (size_t)(k0 + r)*HD_ + s*8);
        }
        cp_commit();
    };
    loadKV(0, 0);

    float o[2][8][4] = {};
    float mi[2][2], li[2][2];
#pragma unroll
    for (int a = 0; a < 2; a++)
#pragma unroll
        for (int b = 0; b < 2; b++) { mi[a][b] = -1e30f; li[a][b] = 0.f; }

    for (int jt = 0; jt < njt; jt++) {
        if (jt + 1 < njt) { loadKV(jt + 1, (jt + 1) % 3); cp_wait<1>(); }
        else              { cp_wait<0>(); }
        __syncthreads();

        const uint32_t Kb = sKV + (uint32_t)(jt % 3) * (FBUF_E * 2);
        const uint32_t Vb = Kb + FKV_E * 2;

        // ---- S = Q @ K^T (log2-scaled) ----
        float s[2][8][4] = {};
#pragma unroll
        for (int ks = 0; ks < 4; ks++) {
            const uint32_t kb2 = (uint32_t)ks * 32;
            uint32_t bf[8][2];
#pragma unroll
            for (int np = 0; np < 4; np++) {
                uint32_t r4[4];
                ldsm_x4(r4, Kb + (uint32_t)(np*16 + rowB) * 144 + kB + kb2);
                bf[np*2  ][0] = r4[0]; bf[np*2  ][1] = r4[1];
                bf[np*2+1][0] = r4[2]; bf[np*2+1][1] = r4[3];
            }
#pragma unroll
            for (int mf = 0; mf < 2; mf++) {
                uint32_t a[4];
                ldsm_x4(a, sQ + (uint32_t)(w*32 + mf*16 + rowA) * 144 + kA + kb2);
#pragma unroll
                for (int nf = 0; nf < 8; nf++)
                    mma_f16(s[mf][nf], a, bf[nf]);
            }
        }

        // ---- causal mask (only last 2 tiles touch the diagonal) ----
        const int k0 = jt << 6;
        if (jt >= njt - 2) {
#pragma unroll
            for (int mf = 0; mf < 2; mf++)
#pragma unroll
                for (int nf = 0; nf < 8; nf++)
#pragma unroll
                    for (int c = 0; c < 4; c++) {
                        const int qr = q0 + w * 32 + mf * 16 + (lane >> 2) + (c >> 1) * 8;
                        const int kc = k0 + nf * 8 + ((lane & 3) << 1) + (c & 1);
                        if (kc > qr) s[mf][nf][c] = -1e30f;
                    }
        }

        // ---- online softmax ----
        float fac[2][2];
#pragma unroll
        for (int mf = 0; mf < 2; mf++)
#pragma unroll
            for (int h = 0; h < 2; h++) {
                float mx = -1e30f;
#pragma unroll
                for (int nf = 0; nf < 8; nf++)
                    mx = fmaxf(mx, fmaxf(s[mf][nf][2*h], s[mf][nf][2*h + 1]));
                mx = fmaxf(mx, __shfl_xor_sync(0xffffffffu, mx, 1));
                mx = fmaxf(mx, __shfl_xor_sync(0xffffffffu, mx, 2));
                const float mn = fmaxf(mi[mf][h], mx);
                fac[mf][h] = ex2f(mi[mf][h] - mn);
                mi[mf][h] = mn;
            }
#pragma unroll
        for (int mf = 0; mf < 2; mf++)
#pragma unroll
            for (int h = 0; h < 2; h++) {
                float r = 0.f;
#pragma unroll
                for (int nf = 0; nf < 8; nf++) {
                    float p0 = ex2f(s[mf][nf][2*h]     - mi[mf][h]);
                    float p1 = ex2f(s[mf][nf][2*h + 1] - mi[mf][h]);
                    s[mf][nf][2*h]     = p0;
                    s[mf][nf][2*h + 1] = p1;
                    r += p0 + p1;
                }
                r += __shfl_xor_sync(0xffffffffu, r, 1);
                r += __shfl_xor_sync(0xffffffffu, r, 2);
                li[mf][h] = li[mf][h] * fac[mf][h] + r;
            }
#pragma unroll
        for (int mf = 0; mf < 2; mf++)
#pragma unroll
            for (int df = 0; df < 8; df++) {
                o[mf][df][0] *= fac[mf][0]; o[mf][df][1] *= fac[mf][0];
                o[mf][df][2] *= fac[mf][1]; o[mf][df][3] *= fac[mf][1];
            }

        // ---- O += P @ V  (V [t][d] in smem; trans ldmatrix fragments) ----
#pragma unroll
        for (int kf = 0; kf < 4; kf++) {
            uint32_t vb[8][2];
#pragma unroll
            for (int np = 0; np < 4; np++) {
                uint32_t r4[4];
                ldsm_x4_t(r4, Vb + (uint32_t)(kf*16 + rowA) * 144 + kA + np*32);
                vb[np*2  ][0] = r4[0]; vb[np*2  ][1] = r4[1];
                vb[np*2+1][0] = r4[2]; vb[np*2+1][1] = r4[3];
            }
#pragma unroll
            for (int mf = 0; mf < 2; mf++) {
                uint32_t pa[4];
                pa[0] = packh2(s[mf][2*kf][0],     s[mf][2*kf][1]);
                pa[1] = packh2(s[mf][2*kf][2],     s[mf][2*kf][3]);
                pa[2] = packh2(s[mf][2*kf + 1][0], s[mf][2*kf + 1][1]);
                pa[3] = packh2(s[mf][2*kf + 1][2], s[mf][2*kf + 1][3]);
#pragma unroll
                for (int df = 0; df < 8; df++)
                    mma_f16(o[mf][df], pa, vb[df]);
            }
        }
    }

    // ---- write O/li -> fp16 A [m][emb] ----
    const int bidx = bh >> 4;
    const int hh   = bh & 15;
    float inv[2][2];
#pragma unroll
    for (int mf = 0; mf < 2; mf++)
#pragma unroll
        for (int h = 0; h < 2; h++) inv[mf][h] = __frcp_rn(li[mf][h]);

#pragma unroll
    for (int mf = 0; mf < 2; mf++)
#pragma unroll
        for (int h = 0; h < 2; h++) {
            const int t = q0 + w * 32 + mf * 16 + (lane >> 2) + h * 8;
            const size_t m = (size_t)bidx * T_ + t;
#pragma unroll
            for (int df = 0; df < 8; df++) {
                const int col = hh * 64 + df * 8 + ((lane & 3) << 1);
                *(uint32_t*)&Aout[m * EMB_ + col] =
                    packh2(o[mf][df][2*h] * inv[mf][h], o[mf][df][2*h + 1] * inv[mf][h]);
            }
        }
}

// ---------------------------------------------------------------------------
extern "C" void kernel_launch(void* const* d_in, const int* in_sizes, int n_in,
                              void* d_out, int out_size)
{
    const float* x  = (const float*)d_in[0];
    const float* Wq = (const float*)d_in[1];
    const float* bq = (const float*)d_in[2];
    const float* Wk = (const float*)d_in[3];
    const float* bk = (const float*)d_in[4];
    const float* Wv = (const float*)d_in[5];
    const float* bv = (const float*)d_in[6];
    const float* Wo = (const float*)d_in[7];
    const float* bo = (const float*)d_in[8];
    float* out = (float*)d_out;

    __half *qh, *kh, *vh, *ah, *x16, *w16, *wo16;
    cudaGetSymbolAddress((void**)&qh,   g_Qh);
    cudaGetSymbolAddress((void**)&kh,   g_Kh);
    cudaGetSymbolAddress((void**)&vh,   g_Vh);
    cudaGetSymbolAddress((void**)&ah,   g_Ah);
    cudaGetSymbolAddress((void**)&x16,  g_x16);
    cudaGetSymbolAddress((void**)&w16,  g_w16);
    cudaGetSymbolAddress((void**)&wo16, g_wo16);

    cudaFuncSetAttribute(flash_h,   cudaFuncAttributeMaxDynamicSharedMemorySize, FLASH_SMEM);
    cudaFuncSetAttribute(gemm_h<0>, cudaFuncAttributeMaxDynamicSharedMemorySize, GEMM_SMEM);
    cudaFuncSetAttribute(gemm_h<1>, cudaFuncAttributeMaxDynamicSharedMemorySize, GEMM_SMEM);

    const int NE = M_ * EMB_;
    const int NW = EMB_ * EMB_;
    const int TOT4 = (NE + 4*NW) / 4;

    tohalf_all<<<(TOT4 + 255)/256, 256>>>(x, Wq, Wk, Wv, Wo, x16, w16, wo16);

    gemm_h<0><<<dim3(EMB_/64, M_/128, 3), 256, GEMM_SMEM>>>(
        x16, w16, bq, bk, bv, qh, kh, vh, nullptr);

    flash_h<<<dim3((T_/128) * BH_), 128, FLASH_SMEM>>>(qh, kh, vh, ah);

    gemm_h<1><<<dim3(EMB_/64, M_/128, 1), 256, GEMM_SMEM>>>(
        ah, wo16, bo, bo, bo, nullptr, nullptr, nullptr, out);
}

// round 14
// speedup vs baseline: 1.0502x; 1.0176x over previous
#include <cuda_runtime.h>
#include <cuda_fp16.h>
#include <stdint.h>

#define T_     2048
#define EMB_   1024
#define HEADS_ 16
#define HD_    64
#define B_     2
#define M_     (B_*T_)      // 4096
#define BH_    (B_*HEADS_)  // 32
#define QSCALE 0.18033688f  // log2(e) / 8

// ---------------- scratch --------------------------------------------------
__device__ __half g_Qh[BH_*T_*HD_];   // [bh][t][d], pre-scaled by QSCALE
__device__ __half g_Kh[BH_*T_*HD_];   // [bh][t][d]
__device__ __half g_Vh[BH_*HD_*T_];   // [bh][d][t]
__device__ __half g_Ah[(size_t)M_*EMB_];   // attention out, fp16 [m][emb]
__device__ __half g_x16[(size_t)M_*EMB_];
__device__ __half g_w16[(size_t)3*EMB_*EMB_];
__device__ __half g_wo16[(size_t)EMB_*EMB_];

// ---------------- helpers ---------------------------------------------------
__device__ __forceinline__ uint32_t smem_u32(const void* p) {
    uint32_t a;
    asm("{ .reg .u64 t; cvta.to.shared.u64 t, %1; cvt.u32.u64 %0, t; }" : "=r"(a) : "l"(p));
    return a;
}
__device__ __forceinline__ void cp16(uint32_t dst, const void* src) {
    asm volatile("cp.async.cg.shared.global [%0], [%1], 16;" :: "r"(dst), "l"(src));
}
__device__ __forceinline__ void cp_commit() { asm volatile("cp.async.commit_group;" ::: "memory"); }
template<int N> __device__ __forceinline__ void cp_wait() {
    asm volatile("cp.async.wait_group %0;" :: "n"(N) : "memory");
}
__device__ __forceinline__ void mma_f16(float* c, const uint32_t* a, const uint32_t* b) {
    asm volatile("mma.sync.aligned.m16n8k16.row.col.f32.f16.f16.f32 "
        "{%0,%1,%2,%3}, {%4,%5,%6,%7}, {%8,%9}, {%0,%1,%2,%3};"
        : "+f"(c[0]), "+f"(c[1]), "+f"(c[2]), "+f"(c[3])
        : "r"(a[0]), "r"(a[1]), "r"(a[2]), "r"(a[3]), "r"(b[0]), "r"(b[1]));
}
__device__ __forceinline__ void ldsm_x4(uint32_t* r, uint32_t addr) {
    asm volatile("ldmatrix.sync.aligned.m8n8.x4.shared.b16 {%0,%1,%2,%3}, [%4];"
        : "=r"(r[0]), "=r"(r[1]), "=r"(r[2]), "=r"(r[3]) : "r"(addr));
}
__device__ __forceinline__ float ex2f(float x) {
    float y; asm("ex2.approx.ftz.f32 %0, %1;" : "=f"(y) : "f"(x)); return y;
}
__device__ __forceinline__ uint32_t packh2(float a, float b) {
    __half2 h = __floats2half2_rn(a, b);
    return *(uint32_t*)&h;
}

// ---------------- fused fp32 -> fp16 convert (one launch) -------------------
__global__ void tohalf_all(const float* __restrict__ x,
                           const float* __restrict__ Wq, const float* __restrict__ Wk,
                           const float* __restrict__ Wv, const float* __restrict__ Wo,
                           __half* __restrict__ x16, __half* __restrict__ w16,
                           __half* __restrict__ wo16)
{
    const int NE = M_ * EMB_;          // 4M
    const int NW = EMB_ * EMB_;        // 1M
    int i = (blockIdx.x * blockDim.x + threadIdx.x) << 2;
    const float* s;
    __half* d;
    if (i < NE) { s = x + i; d = x16 + i; }
    else {
        int j = i - NE;
        if (j < 3 * NW) {
            const int sel = j >> 20;             // NW == 2^20
            const int off = j & (NW - 1);
            s = (sel == 0 ? Wq : (sel == 1 ? Wk : Wv)) + off;
            d = w16 + j;
        } else {
            int off = j - 3 * NW;
            if (off >= NW) return;
            s = Wo + off; d = wo16 + off;
        }
    }
    float4 v = *(const float4*)s;
    __half2* D = (__half2*)d;
    D[0] = __floats2half2_rn(v.x, v.y);
    D[1] = __floats2half2_rn(v.z, v.w);
}

// ---------------- fp16 HMMA GEMM: 128x64 tile, K=1024, 2-stage, ldmatrix ----
#define BK      64
#define NCH     (EMB_/BK)       // 16
#define GST     72              // half stride (64 + 8 pad); 144B rows
#define A_E     (128*GST)
#define B_E     (64*GST)
#define GBUF_E  (A_E + B_E)
#define GEMM_SMEM (2*GBUF_E*2)  // 55296 bytes -> 4 CTAs/SM

template<int MODE>
__global__ void __launch_bounds__(256, 4) gemm_h(
    const __half* __restrict__ A, const __half* __restrict__ W,
    const float* __restrict__ b0, const float* __restrict__ b1,
    const float* __restrict__ b2,
    __half* __restrict__ qo, __half* __restrict__ ko, __half* __restrict__ vo,
    float* __restrict__ fout)
{
    extern __shared__ __half sh[];
    const int tid  = threadIdx.x;
    const int lane = tid & 31;
    const int wid  = tid >> 5;
    const int wm   = wid >> 1;       // 0..3
    const int wn   = wid & 1;        // 0..1
    const int m0   = blockIdx.y << 7;
    const int n0   = blockIdx.x << 6;
    const int z    = (MODE == 0) ? (int)blockIdx.z : 0;

    const __half* Wp  = W + (size_t)z * EMB_ * EMB_;
    const float* bias = (MODE == 0) ? (z == 0 ? b0 : (z == 1 ? b1 : b2)) : b0;

    const uint32_t sb = smem_u32(sh);

    const uint32_t rowA = (uint32_t)(((lane >> 3) & 1) * 8 + (lane & 7));
    const uint32_t kA   = (uint32_t)((lane >> 4) * 16);
    const uint32_t rowB = (uint32_t)((lane >> 4) * 8 + (lane & 7));
    const uint32_t kB   = (uint32_t)(((lane >> 3) & 1) * 16);

    auto load_chunk = [&](int kc, int buf) {
        const uint32_t base = sb + (uint32_t)buf * (GBUF_E * 2);
        const int ke = kc * BK;
#pragma unroll
        for (int it = 0; it < 6; it++) {
            const int idx = tid + (it << 8);
            const int row = idx >> 3;
            const int seg = idx & 7;
            const __half* src = (row < 128)
                ? (A  + (size_t)(m0 + row) * EMB_ + ke + seg * 8)
                : (Wp + (size_t)(n0 + row - 128) * EMB_ + ke + seg * 8);
            cp16(base + (uint32_t)row * 144 + seg * 16, src);
        }
        cp_commit();
    };

    float acc[2][4][4] = {};
    load_chunk(0, 0);

    for (int kc = 0; kc < NCH; kc++) {
        const int buf = kc & 1;
        if (kc + 1 < NCH) { load_chunk(kc + 1, buf ^ 1); cp_wait<1>(); }
        else              { cp_wait<0>(); }
        __syncthreads();

        const uint32_t sAu = sb + (uint32_t)buf * (GBUF_E * 2);
        const uint32_t sBu = sAu + A_E * 2;

#pragma unroll
        for (int ks = 0; ks < 4; ks++) {
            const uint32_t kb2 = (uint32_t)ks * 32;
            uint32_t bf[4][2];
#pragma unroll
            for (int np = 0; np < 2; np++) {
                uint32_t r4[4];
                ldsm_x4(r4, sBu + (uint32_t)(wn*32 + np*16 + rowB) * 144 + kB + kb2);
                bf[np*2  ][0] = r4[0]; bf[np*2  ][1] = r4[1];
                bf[np*2+1][0] = r4[2]; bf[np*2+1][1] = r4[3];
            }
#pragma unroll
            for (int mf = 0; mf < 2; mf++) {
                uint32_t a[4];
                ldsm_x4(a, sAu + (uint32_t)(wm*32 + mf*16 + rowA) * 144 + kA + kb2);
#pragma unroll
                for (int nf = 0; nf < 4; nf++)
                    mma_f16(acc[mf][nf], a, bf[nf]);
            }
        }
        __syncthreads();
    }

    // -------- epilogue --------
#pragma unroll
    for (int mf = 0; mf < 2; mf++) {
#pragma unroll
        for (int nf = 0; nf < 4; nf++) {
#pragma unroll
            for (int h = 0; h < 2; h++) {
                const int m = m0 + wm * 32 + mf * 16 + (lane >> 2) + h * 8;
                const int n = n0 + wn * 32 + nf * 8 + ((lane & 3) << 1);
                const float v0 = acc[mf][nf][h*2 + 0] + bias[n];
                const float v1 = acc[mf][nf][h*2 + 1] + bias[n + 1];
                if (MODE == 0) {
                    const int bb = m >> 11, t = m & (T_ - 1);
                    const int hh = n >> 6,  d = n & 63;
                    const int bh = bb * HEADS_ + hh;
                    if (z == 0) {
                        *(uint32_t*)&qo[((size_t)bh * T_ + t) * HD_ + d] =
                            packh2(v0 * QSCALE, v1 * QSCALE);
                    } else if (z == 1) {
                        *(uint32_t*)&ko[((size_t)bh * T_ + t) * HD_ + d] =
                            packh2(v0, v1);
                    } else {
                        vo[((size_t)bh * HD_ + d    ) * T_ + t] = __float2half(v0);
                        vo[((size_t)bh * HD_ + d + 1) * T_ + t] = __float2half(v1);
                    }
                } else {
                    *(float2*)&fout[(size_t)m * EMB_ + n] = make_float2(v0, v1);
                }
            }
        }
    }
}

// ---------------- HMMA flash attention, 3-stage KV, single-sync, 1D grid ----
#define FST 72
#define FQ_E (128*FST)                      // 9216 halves
#define FKV_E (64*FST)                      // 4608 halves per K (or V) tile
#define FBUF_E (2*FKV_E)                    // K + V per stage
#define FLASH_SMEM ((FQ_E + 3*FBUF_E)*2)    // 73728 bytes -> 3 CTAs/SM

__global__ void __launch_bounds__(128, 3) flash_h(
    const __half* __restrict__ Q, const __half* __restrict__ K,
    const __half* __restrict__ V, __half* __restrict__ Aout)
{
    extern __shared__ __half fsh[];
    __half* Qs  = fsh;                  // [128][72]
    __half* KVs = fsh + FQ_E;           // 3 stages of (K[64][72], V[64][72])

    // global heavy-first: idx 0..31 -> qi=15 (all bh), then qi=14, ...
    const int idx = blockIdx.x;
    const int qi  = (T_/128 - 1) - (idx >> 5);
    const int bh  = idx & 31;
    const int q0  = qi << 7;
    const int tid = threadIdx.x;
    const int lane = tid & 31;
    const int w   = tid >> 5;
    const int njt = 2 * qi + 2;

    const __half* Qg = Q + ((size_t)bh * T_ + q0) * HD_;
    const __half* Kg = K + (size_t)bh * T_ * HD_;
    const __half* Vg = V + (size_t)bh * HD_ * T_;
    const uint32_t sQ  = smem_u32(Qs);
    const uint32_t sKV = smem_u32(KVs);

    const uint32_t rowA = (uint32_t)(((lane >> 3) & 1) * 8 + (lane & 7));
    const uint32_t kA   = (uint32_t)((lane >> 4) * 16);
    const uint32_t rowB = (uint32_t)((lane >> 4) * 8 + (lane & 7));
    const uint32_t kB   = (uint32_t)(((lane >> 3) & 1) * 16);

#pragma unroll
    for (int s = 0; s < 8; s++)
        cp16(sQ + (uint32_t)tid*144 + s*16, Qg + (size_t)tid*HD_ + s*8);
    cp_commit();

    auto loadKV = [&](int jt, int buf) {
        const int k0 = jt << 6;
        const int r  = tid >> 1;
        const int sb_ = (tid & 1) << 2;
        const uint32_t base = sKV + (uint32_t)buf * (FBUF_E * 2);
#pragma unroll
        for (int s = sb_; s < sb_ + 4; s++) {
            cp16(base + (uint32_t)r*144 + s*16, Kg + (size_t)(k0 + r)*HD_ + s*8);
            cp16(base + FKV_E*2 + (uint32_t)r*144 + s*16, Vg + (size_t)r*T_ + k0 + s*8);
        }
        cp_commit();
    };
    loadKV(0, 0);

    float o[2][8][4] = {};
    float mi[2][2], li[2][2];
#pragma unroll
    for (int a = 0; a < 2; a++)
#pragma unroll
        for (int b = 0; b < 2; b++) { mi[a][b] = -1e30f; li[a][b] = 0.f; }

    for (int jt = 0; jt < njt; jt++) {
        if (jt + 1 < njt) { loadKV(jt + 1, (jt + 1) % 3); cp_wait<1>(); }
        else              { cp_wait<0>(); }
        __syncthreads();

        const uint32_t Kb = sKV + (uint32_t)(jt % 3) * (FBUF_E * 2);
        const uint32_t Vb = Kb + FKV_E * 2;

        // ---- S = Q @ K^T (log2-scaled) ----
        float s[2][8][4] = {};
#pragma unroll
        for (int ks = 0; ks < 4; ks++) {
            const uint32_t kb2 = (uint32_t)ks * 32;
            uint32_t bf[8][2];
#pragma unroll
            for (int np = 0; np < 4; np++) {
                uint32_t r4[4];
                ldsm_x4(r4, Kb + (uint32_t)(np*16 + rowB) * 144 + kB + kb2);
                bf[np*2  ][0] = r4[0]; bf[np*2  ][1] = r4[1];
                bf[np*2+1][0] = r4[2]; bf[np*2+1][1] = r4[3];
            }
#pragma unroll
            for (int mf = 0; mf < 2; mf++) {
                uint32_t a[4];
                ldsm_x4(a, sQ + (uint32_t)(w*32 + mf*16 + rowA) * 144 + kA + kb2);
#pragma unroll
                for (int nf = 0; nf < 8; nf++)
                    mma_f16(s[mf][nf], a, bf[nf]);
            }
        }

        // ---- causal mask (only last 2 tiles touch the diagonal) ----
        const int k0 = jt << 6;
        if (jt >= njt - 2) {
#pragma unroll
            for (int mf = 0; mf < 2; mf++)
#pragma unroll
                for (int nf = 0; nf < 8; nf++)
#pragma unroll
                    for (int c = 0; c < 4; c++) {
                        const int qr = q0 + w * 32 + mf * 16 + (lane >> 2) + (c >> 1) * 8;
                        const int kc = k0 + nf * 8 + ((lane & 3) << 1) + (c & 1);
                        if (kc > qr) s[mf][nf][c] = -1e30f;
                    }
        }

        // ---- online softmax ----
        float fac[2][2];
#pragma unroll
        for (int mf = 0; mf < 2; mf++)
#pragma unroll
            for (int h = 0; h < 2; h++) {
                float mx = -1e30f;
#pragma unroll
                for (int nf = 0; nf < 8; nf++)
                    mx = fmaxf(mx, fmaxf(s[mf][nf][2*h], s[mf][nf][2*h + 1]));
                mx = fmaxf(mx, __shfl_xor_sync(0xffffffffu, mx, 1));
                mx = fmaxf(mx, __shfl_xor_sync(0xffffffffu, mx, 2));
                const float mn = fmaxf(mi[mf][h], mx);
                fac[mf][h] = ex2f(mi[mf][h] - mn);
                mi[mf][h] = mn;
            }
#pragma unroll
        for (int mf = 0; mf < 2; mf++)
#pragma unroll
            for (int h = 0; h < 2; h++) {
                float r = 0.f;
#pragma unroll
                for (int nf = 0; nf < 8; nf++) {
                    float p0 = ex2f(s[mf][nf][2*h]     - mi[mf][h]);
                    float p1 = ex2f(s[mf][nf][2*h + 1] - mi[mf][h]);
                    s[mf][nf][2*h]     = p0;
                    s[mf][nf][2*h + 1] = p1;
                    r += p0 + p1;
                }
                r += __shfl_xor_sync(0xffffffffu, r, 1);
                r += __shfl_xor_sync(0xffffffffu, r, 2);
                li[mf][h] = li[mf][h] * fac[mf][h] + r;
            }
#pragma unroll
        for (int mf = 0; mf < 2; mf++)
#pragma unroll
            for (int df = 0; df < 8; df++) {
                o[mf][df][0] *= fac[mf][0]; o[mf][df][1] *= fac[mf][0];
                o[mf][df][2] *= fac[mf][1]; o[mf][df][3] *= fac[mf][1];
            }

        // ---- O += P @ V  (in-register C->A fragment conversion) ----
#pragma unroll
        for (int kf = 0; kf < 4; kf++) {
            const uint32_t kb2 = (uint32_t)kf * 32;
            uint32_t vb[8][2];
#pragma unroll
            for (int np = 0; np < 4; np++) {
                uint32_t r4[4];
                ldsm_x4(r4, Vb + (uint32_t)(np*16 + rowB) * 144 + kB + kb2);
                vb[np*2  ][0] = r4[0]; vb[np*2  ][1] = r4[1];
                vb[np*2+1][0] = r4[2]; vb[np*2+1][1] = r4[3];
            }
#pragma unroll
            for (int mf = 0; mf < 2; mf++) {
                uint32_t pa[4];
                pa[0] = packh2(s[mf][2*kf][0],     s[mf][2*kf][1]);
                pa[1] = packh2(s[mf][2*kf][2],     s[mf][2*kf][3]);
                pa[2] = packh2(s[mf][2*kf + 1][0], s[mf][2*kf + 1][1]);
                pa[3] = packh2(s[mf][2*kf + 1][2], s[mf][2*kf + 1][3]);
#pragma unroll
                for (int df = 0; df < 8; df++)
                    mma_f16(o[mf][df], pa, vb[df]);
            }
        }
    }

    // ---- write O/li -> fp16 A [m][emb] ----
    const int bidx = bh >> 4;
    const int hh   = bh & 15;
    float inv[2][2];
#pragma unroll
    for (int mf = 0; mf < 2; mf++)
#pragma unroll
        for (int h = 0; h < 2; h++) inv[mf][h] = __frcp_rn(li[mf][h]);

#pragma unroll
    for (int mf = 0; mf < 2; mf++)
#pragma unroll
        for (int h = 0; h < 2; h++) {
            const int t = q0 + w * 32 + mf * 16 + (lane >> 2) + h * 8;
            const size_t m = (size_t)bidx * T_ + t;
#pragma unroll
            for (int df = 0; df < 8; df++) {
                const int col = hh * 64 + df * 8 + ((lane & 3) << 1);
                *(uint32_t*)&Aout[m * EMB_ + col] =
                    packh2(o[mf][df][2*h] * inv[mf][h], o[mf][df][2*h + 1] * inv[mf][h]);
            }
        }
}

// ---------------------------------------------------------------------------
extern "C" void kernel_launch(void* const* d_in, const int* in_sizes, int n_in,
                              void* d_out, int out_size)
{
    const float* x  = (const float*)d_in[0];
    const float* Wq = (const float*)d_in[1];
    const float* bq = (const float*)d_in[2];
    const float* Wk = (const float*)d_in[3];
    const float* bk = (const float*)d_in[4];
    const float* Wv = (const float*)d_in[5];
    const float* bv = (const float*)d_in[6];
    const float* Wo = (const float*)d_in[7];
    const float* bo = (const float*)d_in[8];
    float* out = (float*)d_out;

    __half *qh, *kh, *vh, *ah, *x16, *w16, *wo16;
    cudaGetSymbolAddress((void**)&qh,   g_Qh);
    cudaGetSymbolAddress((void**)&kh,   g_Kh);
    cudaGetSymbolAddress((void**)&vh,   g_Vh);
    cudaGetSymbolAddress((void**)&ah,   g_Ah);
    cudaGetSymbolAddress((void**)&x16,  g_x16);
    cudaGetSymbolAddress((void**)&w16,  g_w16);
    cudaGetSymbolAddress((void**)&wo16, g_wo16);

    cudaFuncSetAttribute(flash_h,   cudaFuncAttributeMaxDynamicSharedMemorySize, FLASH_SMEM);
    cudaFuncSetAttribute(gemm_h<0>, cudaFuncAttributeMaxDynamicSharedMemorySize, GEMM_SMEM);
    cudaFuncSetAttribute(gemm_h<1>, cudaFuncAttributeMaxDynamicSharedMemorySize, GEMM_SMEM);

    const int NE = M_ * EMB_;
    const int NW = EMB_ * EMB_;
    const int TOT4 = (NE + 4*NW) / 4;

    tohalf_all<<<(TOT4 + 255)/256, 256>>>(x, Wq, Wk, Wv, Wo, x16, w16, wo16);

    gemm_h<0><<<dim3(EMB_/64, M_/128, 3), 256, GEMM_SMEM>>>(
        x16, w16, bq, bk, bv, qh, kh, vh, nullptr);

    flash_h<<<dim3((T_/128) * BH_), 128, FLASH_SMEM>>>(qh, kh, vh, ah);

    gemm_h<1><<<dim3(EMB_/64, M_/128, 1), 256, GEMM_SMEM>>>(
        ah, wo16, bo, bo, bo, nullptr, nullptr, nullptr, out);
}